// round 4
// baseline (speedup 1.0000x reference)
#include <cuda_runtime.h>

// NoQmix: q_tot[b] = sum_j agent_qs[b, j]
//
// Derivation (exact, not approximate):
//   attention = softmax(e, axis=1)  =>  sum_i attention[b,i,j] == 1 for every (b,j)
//   (holds regardless of leaky-ReLU / adjacency masking: a fully-masked column
//    softmaxes to uniform 1/N, which still sums to 1.)
//   q_tot[b]  = sum_{i,j} attention[b,i,j] * qs[b,j]
//             = sum_j qs[b,j] * (sum_i attention[b,i,j])
//             = sum_j qs[b,j]
// features/W/a GEMMs and the adjacency mask cancel out of the output.
// Only agent_qs (input index 1, shape [4096, 64] fp32) matters:
// total traffic = 1.05 MB read + 16 KB write.

static constexpr int B_ROWS = 4096;
static constexpr int N_AGENTS = 64;

__global__ void noqmix_rowsum_kernel(const float* __restrict__ qs,
                                     float* __restrict__ out) {
    // 16 lanes per row, each lane loads one float4 (4 floats): 16*4 = 64 = N.
    // 2 rows per warp, 8 warps per block -> 16 rows per block.
    // Grid is exact (4096 / 16 = 256 blocks), so no bounds guard is needed.
    const int gwarp = (blockIdx.x * blockDim.x + threadIdx.x) >> 5;
    const int lane  = threadIdx.x & 31;
    const int sub   = lane >> 4;      // which of the 2 rows in this warp
    const int slane = lane & 15;      // lane within the 16-lane row group
    const int row   = gwarp * 2 + sub;

    const float4* p = reinterpret_cast<const float4*>(qs) + (size_t)row * (N_AGENTS / 4);
    float4 v = p[slane];
    float s = (v.x + v.y) + (v.z + v.w);

    // Butterfly reduce within the 16-lane group (xor offsets stay inside it).
    s += __shfl_xor_sync(0xffffffffu, s, 8);
    s += __shfl_xor_sync(0xffffffffu, s, 4);
    s += __shfl_xor_sync(0xffffffffu, s, 2);
    s += __shfl_xor_sync(0xffffffffu, s, 1);

    if (slane == 0) out[row] = s;
}

extern "C" void kernel_launch(void* const* d_in, const int* in_sizes, int n_in,
                              void* d_out, int out_size) {
    // Input order: features(0), agent_qs(1), adj(2), states(3), W(4), a(5).
    const float* agent_qs = (const float*)d_in[1];
    float* out = (float*)d_out;

    // 4096 rows, 16 rows per block -> exactly 256 blocks of 256 threads.
    const int threads = 256;
    const int rows_per_block = (threads / 32) * 2;                      // 16
    const int blocks = B_ROWS / rows_per_block;                         // 256
    noqmix_rowsum_kernel<<<blocks, threads>>>(agent_qs, out);
}